// round 5
// baseline (speedup 1.0000x reference)
#include <cuda_runtime.h>
#include <cuda_fp16.h>

#define T_STEPS 256
#define NN      64
#define HH      512
#define DT_C    0.01f
#define NBLK    256
#define NTHR    256
#define RES_H   8                                   // Wh resident j-iters (last 8 of 32)
#define RES_X   16                                  // Wx resident j-iters (first 16 of 32)
#define SLOTS   (RES_H + RES_X)                     // 24 slots per half-warp
#define DYN_SMEM (16 * SLOTS * 16 * 16)             // 16 hw * 24 * 16 lanes * 16B = 98304

// 64 MiB of fp16 transposed weights: layout [n][j][i]
__device__ __half g_Wh[(size_t)NN * HH * HH];
__device__ __half g_Wx[(size_t)NN * HH * HH];
__device__ unsigned g_state_cnt;        // +1 per block per step (monotonic)
__device__ unsigned g_hy_cnt[NN];       // +1 per sibling per step
__device__ unsigned g_ins_cnt[NN];      // +1 per sibling per step

// ---------------------------------------------------------------------------
__device__ __forceinline__ void arrive_rel(unsigned* ctr)
{
    asm volatile("red.release.gpu.add.u32 [%0], 1;" :: "l"(ctr) : "memory");
}
__device__ __forceinline__ unsigned ld_acq(unsigned* ctr)
{
    unsigned v;
    asm volatile("ld.acquire.gpu.u32 %0, [%1];" : "=r"(v) : "l"(ctr) : "memory");
    return v;
}
__device__ __forceinline__ void spin_until(unsigned* ctr, unsigned target)
{
    if (ld_acq(ctr) >= target) return;
    while (ld_acq(ctr) < target) __nanosleep(20);
}

// ---------------------------------------------------------------------------
// fp32 [n][i][j]  ->  fp16 [n][j][i]   (transpose + convert, tiled)
// ---------------------------------------------------------------------------
__global__ void convert_transpose_kernel(const float* __restrict__ src, int which)
{
    __shared__ float tile[32][33];
    __half* dst = which ? g_Wx : g_Wh;
    const int nmat = blockIdx.z;
    const float* s = src + (size_t)nmat * HH * HH;
    __half*      d = dst + (size_t)nmat * HH * HH;
    const int x0 = blockIdx.x * 32;
    const int y0 = blockIdx.y * 32;
    #pragma unroll
    for (int k = threadIdx.y; k < 32; k += 8)
        tile[k][threadIdx.x] = s[(size_t)(y0 + k) * HH + x0 + threadIdx.x];
    __syncthreads();
    #pragma unroll
    for (int k = threadIdx.y; k < 32; k += 8)
        d[(size_t)(x0 + k) * HH + y0 + threadIdx.x] = __float2half_rn(tile[threadIdx.x][k]);
}

// ---------------------------------------------------------------------------
__global__ void init_out_kernel(const float* __restrict__ x,
                                const float* __restrict__ init_states,
                                float* __restrict__ states,
                                float* __restrict__ ins)
{
    const int i = blockIdx.x * blockDim.x + threadIdx.x;
    if (i < NN * 2 * HH) states[i] = init_states[i];
    if (i < NN * HH)     ins[i]    = x[i];
    if (i < NN)          { g_hy_cnt[i] = 0; g_ins_cnt[i] = 0; }
    if (i == 0)          g_state_cnt = 0;
}

// ---------------------------------------------------------------------------
__device__ __forceinline__ void fma8(float* acc, uint4 a, float v)
{
    float2 f;
    f = __half22float2(*reinterpret_cast<__half2*>(&a.x)); acc[0] += f.x * v; acc[1] += f.y * v;
    f = __half22float2(*reinterpret_cast<__half2*>(&a.y)); acc[2] += f.x * v; acc[3] += f.y * v;
    f = __half22float2(*reinterpret_cast<__half2*>(&a.z)); acc[4] += f.x * v; acc[5] += f.y * v;
    f = __half22float2(*reinterpret_cast<__half2*>(&a.w)); acc[6] += f.x * v; acc[7] += f.y * v;
}

// ---------------------------------------------------------------------------
// persistent RNN: 256 blocks = 4 per neuron (each 128 outputs), 2 blocks/SM.
// tid0-only counter polling; asymmetric weight residency:
//   Wh: 24 iters streamed from L2 (inside the global-wait window) + 8 resident
//       (covering the sibling-ins wait); Wx: 16 resident + 16 streamed.
// ---------------------------------------------------------------------------
__global__ void __launch_bounds__(NTHR, 2) rnn_kernel(
    const float* __restrict__ x,      // [T][N][H]
    const float* __restrict__ C,      // [N][N]
    const float* __restrict__ b,      // [N][H]
    float* __restrict__ states,       // [T+1][N][2][H]
    float* __restrict__ ins)          // [T+1][N][H]
{
    extern __shared__ __align__(16) unsigned char dynsmem[];
    uint4* sres = reinterpret_cast<uint4*>(dynsmem);

    __shared__ __align__(16) float sh_hy[HH];
    __shared__ __align__(16) float sh_ins[HH];
    __shared__ float sh_C[NN];
    __shared__ float sh_cm[2 * 128];
    __shared__ float sh_part[8 * 128];

    const int bid   = blockIdx.x;
    const int n     = bid >> 2;
    const int ibase = (bid & 3) * 128;
    const int tid   = threadIdx.x;
    const int warp  = tid >> 5;
    const int lane  = tid & 31;
    const int hw    = lane >> 4;            // half-warp: contiguous 32-j block
    const int li    = lane & 15;            // i-chunk (8 halves via uint4)
    const int jb    = warp * 64 + hw * 32;  // this half-warp's j-base

    if (tid < NN) sh_C[tid] = C[n * NN + tid];
    const float bias = (tid < 128) ? b[n * HH + ibase + tid] : 0.0f;

    const __half* pWh = g_Wh + (size_t)n * HH * HH + (size_t)jb * HH + ibase + li * 8;
    const __half* pWx = g_Wx + (size_t)n * HH * HH + (size_t)jb * HH + ibase + li * 8;
    const int sb = ((warp * 2 + hw) * SLOTS) * 16 + li;   // + slot*16

    // ---- stage resident weights into shared (once) ----
    #pragma unroll
    for (int k = 0; k < RES_H; ++k)          // Wh iters 24..31 -> slots 0..7
        sres[sb + k * 16] = *reinterpret_cast<const uint4*>(pWh + (size_t)(24 + k) * HH);
    #pragma unroll
    for (int k = 0; k < RES_X; ++k)          // Wx iters 0..15 -> slots 8..23
        sres[sb + (RES_H + k) * 16] = *reinterpret_cast<const uint4*>(pWx + (size_t)k * HH);

    // hz for own 128 outputs lives in a register across all steps
    float hz_r = (tid < 128) ? states[(n * 2 + 1) * HH + ibase + tid] : 0.0f;

    __syncthreads();

    for (int t = 0; t < T_STEPS; ++t) {
        const float* st  = states + (size_t)t * NN * 2 * HH;
        float*       stn = states + (size_t)(t + 1) * NN * 2 * HH;

        // ---- wait siblings' hy(t) chunks (cheap: 4 arrivals) ---------------
        if (t > 0) {
            if (tid == 0) spin_until(&g_hy_cnt[n], 4u * (unsigned)t);
            __syncthreads();                                        // bar1
        }
        reinterpret_cast<float2*>(sh_hy)[tid] =
            reinterpret_cast<const float2*>(st + n * 2 * HH)[tid];
        const float xv = (tid < 128) ? x[((size_t)t * NN + n) * HH + ibase + tid] : 0.0f;
        __syncthreads();                                            // bar2

        float acc[8];
        #pragma unroll
        for (int k = 0; k < 8; ++k) acc[k] = 0.0f;

        // ---- Wh.hy: 24 streamed iters (hide the global state wait) ---------
        #pragma unroll 2
        for (int g = 0; g < 6; ++g) {
            const float4 hv = *reinterpret_cast<const float4*>(&sh_hy[jb + g * 4]);
            uint4 w0 = *reinterpret_cast<const uint4*>(pWh + (size_t)(g * 4 + 0) * HH);
            uint4 w1 = *reinterpret_cast<const uint4*>(pWh + (size_t)(g * 4 + 1) * HH);
            uint4 w2 = *reinterpret_cast<const uint4*>(pWh + (size_t)(g * 4 + 2) * HH);
            uint4 w3 = *reinterpret_cast<const uint4*>(pWh + (size_t)(g * 4 + 3) * HH);
            fma8(acc, w0, hv.x);
            fma8(acc, w1, hv.y);
            fma8(acc, w2, hv.z);
            fma8(acc, w3, hv.w);
        }

        // ---- global wait: all 256 blocks finished step t-1 ------------------
        if (t > 0) {
            if (tid == 0) spin_until(&g_state_cnt, 256u * (unsigned)t);
            __syncthreads();                                        // bar3
        }

        // ---- distributed C-mix: ins chunk for own 128 j's ------------------
        {
            const int jloc = tid & 127;
            float cm = 0.0f;
            if (t > 0) {
                const int mb = (tid < 128) ? 0 : 32;
                const float* sp = st + (size_t)(2 * mb) * HH + ibase + jloc;
                #pragma unroll 16
                for (int m = 0; m < 32; ++m)
                    cm += sh_C[mb + m] * sp[(size_t)m * 2 * HH];
            }
            sh_cm[tid] = cm;
        }
        __syncthreads();                                            // bar4
        if (tid < 128) {
            const float v = (t > 0) ? (sh_cm[tid] + sh_cm[tid + 128]) * xv : 0.0f;
            ins[((size_t)(t + 1) * NN + n) * HH + ibase + tid] = v;
        }
        __syncthreads();                                            // bar5
        if (tid == 0) arrive_rel(&g_ins_cnt[n]);

        // ---- Wh.hy: 8 resident iters (hide sibling ins skew) ---------------
        {
            const float4 h0 = *reinterpret_cast<const float4*>(&sh_hy[jb + 24]);
            const float4 h1 = *reinterpret_cast<const float4*>(&sh_hy[jb + 28]);
            fma8(acc, sres[sb + 0 * 16], h0.x);
            fma8(acc, sres[sb + 1 * 16], h0.y);
            fma8(acc, sres[sb + 2 * 16], h0.z);
            fma8(acc, sres[sb + 3 * 16], h0.w);
            fma8(acc, sres[sb + 4 * 16], h1.x);
            fma8(acc, sres[sb + 5 * 16], h1.y);
            fma8(acc, sres[sb + 6 * 16], h1.z);
            fma8(acc, sres[sb + 7 * 16], h1.w);
        }

        // ---- gather full ins(t+1) ------------------------------------------
        if (tid == 0) spin_until(&g_ins_cnt[n], 4u * (unsigned)(t + 1));
        __syncthreads();                                            // bar6
        reinterpret_cast<float2*>(sh_ins)[tid] =
            reinterpret_cast<const float2*>(ins + ((size_t)(t + 1) * NN + n) * HH)[tid];
        __syncthreads();                                            // bar7

        // ---- Wx.ins: 16 streamed iters first (LDG MLP), then 16 resident ---
        #pragma unroll 2
        for (int g = 4; g < 8; ++g) {
            const float4 iv = *reinterpret_cast<const float4*>(&sh_ins[jb + g * 4]);
            uint4 w0 = *reinterpret_cast<const uint4*>(pWx + (size_t)(g * 4 + 0) * HH);
            uint4 w1 = *reinterpret_cast<const uint4*>(pWx + (size_t)(g * 4 + 1) * HH);
            uint4 w2 = *reinterpret_cast<const uint4*>(pWx + (size_t)(g * 4 + 2) * HH);
            uint4 w3 = *reinterpret_cast<const uint4*>(pWx + (size_t)(g * 4 + 3) * HH);
            fma8(acc, w0, iv.x);
            fma8(acc, w1, iv.y);
            fma8(acc, w2, iv.z);
            fma8(acc, w3, iv.w);
        }
        #pragma unroll 4
        for (int g = 0; g < 4; ++g) {
            const float4 iv = *reinterpret_cast<const float4*>(&sh_ins[jb + g * 4]);
            fma8(acc, sres[sb + (RES_H + g * 4 + 0) * 16], iv.x);
            fma8(acc, sres[sb + (RES_H + g * 4 + 1) * 16], iv.y);
            fma8(acc, sres[sb + (RES_H + g * 4 + 2) * 16], iv.z);
            fma8(acc, sres[sb + (RES_H + g * 4 + 3) * 16], iv.w);
        }

        // ---- reduce: half-warp pair via shfl, then 8 warps via shared -------
        #pragma unroll
        for (int k = 0; k < 8; ++k)
            acc[k] += __shfl_down_sync(0xffffffffu, acc[k], 16);
        if (hw == 0) {
            #pragma unroll
            for (int k = 0; k < 8; ++k)
                sh_part[warp * 128 + li * 8 + k] = acc[k];
        }
        __syncthreads();                                            // bar8

        // ---- state update (hz carried in registers) ------------------------
        if (tid < 128) {
            float s = bias;
            #pragma unroll
            for (int w2 = 0; w2 < 8; ++w2) s += sh_part[w2 * 128 + tid];
            const float hy   = sh_hy[ibase + tid];
            const float hz_n = hz_r + DT_C * (tanhf(s) - hy - hz_r);   // GAMMA=EPS=1
            const float hy_n = hy + DT_C * hz_n;
            hz_r = hz_n;
            stn[(n * 2 + 0) * HH + ibase + tid] = hy_n;
            stn[(n * 2 + 1) * HH + ibase + tid] = hz_n;
        }
        __syncthreads();                                            // bar9
        if (tid == 0) {
            arrive_rel(&g_hy_cnt[n]);      // siblings may start next Wh.hy
            arrive_rel(&g_state_cnt);      // everyone may start next C-mix
        }
    }
}

// ---------------------------------------------------------------------------
extern "C" void kernel_launch(void* const* d_in, const int* in_sizes, int n_in,
                              void* d_out, int out_size)
{
    const float* x   = (const float*)d_in[0];   // (256, 64, 512)
    const float* C   = (const float*)d_in[1];   // (64, 64)
    const float* Wh  = (const float*)d_in[2];   // (64, 512, 512)
    const float* Wx  = (const float*)d_in[3];   // (64, 512, 512)
    const float* b   = (const float*)d_in[4];   // (64, 512)
    const float* s0  = (const float*)d_in[5];   // (64, 2, 512)

    float* out    = (float*)d_out;
    float* states = out;                                          // (257,64,2,512)
    float* ins    = out + (size_t)(T_STEPS + 1) * NN * 2 * HH;    // (257,64,512)

    cudaFuncSetAttribute(rnn_kernel, cudaFuncAttributeMaxDynamicSharedMemorySize, DYN_SMEM);

    dim3 tb(32, 8, 1), tg(16, 16, NN);
    convert_transpose_kernel<<<tg, tb>>>(Wh, 0);
    convert_transpose_kernel<<<tg, tb>>>(Wx, 1);
    init_out_kernel<<<(NN * 2 * HH + 255) / 256, 256>>>(x, s0, states, ins);
    rnn_kernel<<<NBLK, NTHR, DYN_SMEM>>>(x, C, b, states, ins);
}

// round 6
// speedup vs baseline: 1.4634x; 1.4634x over previous
#include <cuda_runtime.h>
#include <cuda_bf16.h>

#define T_STEPS 256
#define NN      64
#define HH      512
#define DT_C    0.01f
#define NBLK    256
#define NTHR    256
#define RES_IT  12                                  // shared-resident j-iters (of 32) per warp
#define DYN_SMEM (8 * RES_IT * 2 * 512)             // 98304 B per block

// 64 MiB of bf16 transposed weights: layout [n][j][i]
__device__ __nv_bfloat16 g_Wh[(size_t)NN * HH * HH];
__device__ __nv_bfloat16 g_Wx[(size_t)NN * HH * HH];
__device__ unsigned g_state_cnt;        // +1 per block per step (monotonic)
__device__ unsigned g_hy_cnt[NN];       // +1 per sibling per step
__device__ unsigned g_ins_cnt[NN];      // +1 per sibling per step

// ---------------------------------------------------------------------------
__device__ __forceinline__ void arrive_rel(unsigned* ctr)
{
    asm volatile("red.release.gpu.add.u32 [%0], 1;" :: "l"(ctr) : "memory");
}
__device__ __forceinline__ unsigned ld_acq(unsigned* ctr)
{
    unsigned v;
    asm volatile("ld.acquire.gpu.u32 %0, [%1];" : "=r"(v) : "l"(ctr) : "memory");
    return v;
}
__device__ __forceinline__ void spin_until(unsigned* ctr, unsigned target)
{
    if (ld_acq(ctr) >= target) return;
    while (ld_acq(ctr) < target) __nanosleep(20);
}

// ---------------------------------------------------------------------------
// fp32 [n][i][j]  ->  bf16 [n][j][i]   (transpose + convert, tiled)
// ---------------------------------------------------------------------------
__global__ void convert_transpose_kernel(const float* __restrict__ src, int which)
{
    __shared__ float tile[32][33];
    __nv_bfloat16* dst = which ? g_Wx : g_Wh;
    const int nmat = blockIdx.z;
    const float* s = src + (size_t)nmat * HH * HH;
    __nv_bfloat16* d = dst + (size_t)nmat * HH * HH;
    const int x0 = blockIdx.x * 32;
    const int y0 = blockIdx.y * 32;
    #pragma unroll
    for (int k = threadIdx.y; k < 32; k += 8)
        tile[k][threadIdx.x] = s[(size_t)(y0 + k) * HH + x0 + threadIdx.x];
    __syncthreads();
    #pragma unroll
    for (int k = threadIdx.y; k < 32; k += 8)
        d[(size_t)(x0 + k) * HH + y0 + threadIdx.x] =
            __float2bfloat16_rn(tile[threadIdx.x][k]);
}

// ---------------------------------------------------------------------------
__global__ void init_out_kernel(const float* __restrict__ x,
                                const float* __restrict__ init_states,
                                float* __restrict__ states,
                                float* __restrict__ ins)
{
    const int i = blockIdx.x * blockDim.x + threadIdx.x;
    if (i < NN * 2 * HH) states[i] = init_states[i];
    if (i < NN * HH)     ins[i]    = x[i];
    if (i < NN)          { g_hy_cnt[i] = 0; g_ins_cnt[i] = 0; }
    if (i == 0)          g_state_cnt = 0;
}

// ---------------------------------------------------------------------------
// 8 MACs from 8 bf16 weights (one uint4). bf16 -> fp32 is pure ALU-pipe
// bit surgery (SHF / LOP3), no F2F converter ops.
__device__ __forceinline__ float bflo(unsigned u) { return __uint_as_float(u << 16); }
__device__ __forceinline__ float bfhi(unsigned u) { return __uint_as_float(u & 0xffff0000u); }

__device__ __forceinline__ void fma8(float* acc, uint4 a, float v)
{
    acc[0] += bflo(a.x) * v; acc[1] += bfhi(a.x) * v;
    acc[2] += bflo(a.y) * v; acc[3] += bfhi(a.y) * v;
    acc[4] += bflo(a.z) * v; acc[5] += bfhi(a.z) * v;
    acc[6] += bflo(a.w) * v; acc[7] += bfhi(a.w) * v;
}

// ---------------------------------------------------------------------------
// persistent RNN: 256 blocks = 4 per neuron (each 128 outputs), 2 blocks/SM.
// No blocking grid barrier: monotonic acquire/release counters, every wait
// hidden behind independent GEMV work.  (Structure identical to R3.)
// ---------------------------------------------------------------------------
__global__ void __launch_bounds__(NTHR, 2) rnn_kernel(
    const float* __restrict__ x,      // [T][N][H]
    const float* __restrict__ C,      // [N][N]
    const float* __restrict__ b,      // [N][H]
    float* __restrict__ states,       // [T+1][N][2][H]
    float* __restrict__ ins)          // [T+1][N][H]
{
    extern __shared__ __align__(16) unsigned char dynsmem[];
    uint4* sres = reinterpret_cast<uint4*>(dynsmem);

    __shared__ float sh_hy[HH];
    __shared__ float sh_ins[HH];
    __shared__ float sh_C[NN];
    __shared__ float sh_cm[2 * 128];
    __shared__ float sh_part[8 * 128];

    const int bid   = blockIdx.x;
    const int n     = bid >> 2;
    const int ibase = (bid & 3) * 128;
    const int tid   = threadIdx.x;
    const int warp  = tid >> 5;
    const int lane  = tid & 31;
    const int hw    = lane >> 4;      // row parity within iter
    const int li    = lane & 15;      // i-chunk (8 bf16 via uint4)
    const int wbase = warp * 64;      // warp's j-range start

    if (tid < NN) sh_C[tid] = C[n * NN + tid];
    const float bias = (tid < 128) ? b[n * HH + ibase + tid] : 0.0f;

    const __nv_bfloat16* pWh = g_Wh + (size_t)n * HH * HH + (size_t)(wbase + hw) * HH + ibase + li * 8;
    const __nv_bfloat16* pWx = g_Wx + (size_t)n * HH * HH + (size_t)(wbase + hw) * HH + ibase + li * 8;

    // ---- stage resident weights into shared (once) ----
    for (int it = 0; it < RES_IT; ++it) {
        sres[((warp * RES_IT + it) * 2 + 0) * 32 + hw * 16 + li] =
            *reinterpret_cast<const uint4*>(pWh + (size_t)it * 2 * HH);
        sres[((warp * RES_IT + it) * 2 + 1) * 32 + hw * 16 + li] =
            *reinterpret_cast<const uint4*>(pWx + (size_t)it * 2 * HH);
    }

    // hz for own 128 outputs lives in a register across all steps
    float hz_r = (tid < 128) ? states[(n * 2 + 1) * HH + ibase + tid] : 0.0f;

    __syncthreads();

    for (int t = 0; t < T_STEPS; ++t) {
        const float* st  = states + (size_t)t * NN * 2 * HH;
        float*       stn = states + (size_t)(t + 1) * NN * 2 * HH;

        // ---- wait siblings' hy(t) chunks (cheap: 4 arrivals, usually done) --
        if (t > 0) {
            if (tid == 0) spin_until(&g_hy_cnt[n], 4u * (unsigned)t);
            __syncthreads();
        }
        reinterpret_cast<float2*>(sh_hy)[tid] =
            reinterpret_cast<const float2*>(st + n * 2 * HH)[tid];
        const float xv = (tid < 128) ? x[((size_t)t * NN + n) * HH + ibase + tid] : 0.0f;
        __syncthreads();

        float acc[8];
        #pragma unroll
        for (int k = 0; k < 8; ++k) acc[k] = 0.0f;

        // ---- Wh.hy global-resident iters: hides the global state wait ------
        #pragma unroll 5
        for (int it = RES_IT; it < 32; ++it) {
            const float v = sh_hy[wbase + 2 * it + hw];
            fma8(acc, *reinterpret_cast<const uint4*>(pWh + (size_t)it * 2 * HH), v);
        }

        // ---- global wait: all 256 blocks finished step t-1 ------------------
        if (t > 0) {
            if (tid == 0) spin_until(&g_state_cnt, 256u * (unsigned)t);
            __syncthreads();
        }

        // ---- distributed C-mix: ins chunk for own 128 j's ------------------
        {
            const int jloc = tid & 127;
            float cm = 0.0f;
            if (t > 0) {
                const int mb = (tid < 128) ? 0 : 32;
                const float* sp = st + (size_t)(2 * mb) * HH + ibase + jloc;
                #pragma unroll 8
                for (int m = 0; m < 32; ++m)
                    cm += sh_C[mb + m] * sp[(size_t)m * 2 * HH];
            }
            sh_cm[tid] = cm;
        }
        __syncthreads();
        if (tid < 128) {
            const float v = (t > 0) ? (sh_cm[tid] + sh_cm[tid + 128]) * xv : 0.0f;
            ins[((size_t)(t + 1) * NN + n) * HH + ibase + tid] = v;
        }
        __syncthreads();
        if (tid == 0) arrive_rel(&g_ins_cnt[n]);

        // ---- Wh.hy shared-resident iters: hides the sibling ins wait -------
        #pragma unroll
        for (int it = 0; it < RES_IT; ++it) {
            const float v = sh_hy[wbase + 2 * it + hw];
            fma8(acc, sres[((warp * RES_IT + it) * 2 + 0) * 32 + hw * 16 + li], v);
        }

        // ---- gather full ins(t+1) ------------------------------------------
        if (tid == 0) spin_until(&g_ins_cnt[n], 4u * (unsigned)(t + 1));
        __syncthreads();
        reinterpret_cast<float2*>(sh_ins)[tid] =
            reinterpret_cast<const float2*>(ins + ((size_t)(t + 1) * NN + n) * HH)[tid];
        __syncthreads();

        // ---- Wx.ins --------------------------------------------------------
        #pragma unroll
        for (int it = 0; it < RES_IT; ++it) {
            const float v = sh_ins[wbase + 2 * it + hw];
            fma8(acc, sres[((warp * RES_IT + it) * 2 + 1) * 32 + hw * 16 + li], v);
        }
        #pragma unroll 5
        for (int it = RES_IT; it < 32; ++it) {
            const float v = sh_ins[wbase + 2 * it + hw];
            fma8(acc, *reinterpret_cast<const uint4*>(pWx + (size_t)it * 2 * HH), v);
        }

        // ---- reduce: half-warp pair, then 8 warps via shared ----------------
        #pragma unroll
        for (int k = 0; k < 8; ++k)
            acc[k] += __shfl_down_sync(0xffffffffu, acc[k], 16);
        if (hw == 0) {
            #pragma unroll
            for (int k = 0; k < 8; ++k)
                sh_part[warp * 128 + li * 8 + k] = acc[k];
        }
        __syncthreads();

        // ---- state update (hz carried in registers) ------------------------
        if (tid < 128) {
            float s = bias;
            #pragma unroll
            for (int w2 = 0; w2 < 8; ++w2) s += sh_part[w2 * 128 + tid];
            const float hy   = sh_hy[ibase + tid];
            const float hz_n = hz_r + DT_C * (tanhf(s) - hy - hz_r);   // GAMMA=EPS=1
            const float hy_n = hy + DT_C * hz_n;
            hz_r = hz_n;
            stn[(n * 2 + 0) * HH + ibase + tid] = hy_n;
            stn[(n * 2 + 1) * HH + ibase + tid] = hz_n;
        }
        __syncthreads();
        if (tid == 0) {
            arrive_rel(&g_hy_cnt[n]);      // siblings may start next Wh.hy
            arrive_rel(&g_state_cnt);      // everyone may start next C-mix
        }
    }
}

// ---------------------------------------------------------------------------
extern "C" void kernel_launch(void* const* d_in, const int* in_sizes, int n_in,
                              void* d_out, int out_size)
{
    const float* x   = (const float*)d_in[0];   // (256, 64, 512)
    const float* C   = (const float*)d_in[1];   // (64, 64)
    const float* Wh  = (const float*)d_in[2];   // (64, 512, 512)
    const float* Wx  = (const float*)d_in[3];   // (64, 512, 512)
    const float* b   = (const float*)d_in[4];   // (64, 512)
    const float* s0  = (const float*)d_in[5];   // (64, 2, 512)

    float* out    = (float*)d_out;
    float* states = out;                                          // (257,64,2,512)
    float* ins    = out + (size_t)(T_STEPS + 1) * NN * 2 * HH;    // (257,64,512)

    cudaFuncSetAttribute(rnn_kernel, cudaFuncAttributeMaxDynamicSharedMemorySize, DYN_SMEM);

    dim3 tb(32, 8, 1), tg(16, 16, NN);
    convert_transpose_kernel<<<tg, tb>>>(Wh, 0);
    convert_transpose_kernel<<<tg, tb>>>(Wx, 1);
    init_out_kernel<<<(NN * 2 * HH + 255) / 256, 256>>>(x, s0, states, ins);
    rnn_kernel<<<NBLK, NTHR, DYN_SMEM>>>(x, C, b, states, ins);
}